// round 13
// baseline (speedup 1.0000x reference)
#include <cuda_runtime.h>
#include <math.h>

#define BMAX 8192
#define NJC 64
#define IT 128

// h1 padded layout (R8 win): row stride 22, channel stride 352.
#define H1S 22
#define H1C 352

// ---------------- scratch (device globals: no allocation allowed) ----------------
__device__ float  g_feat[BMAX * 784];
__device__ __align__(16) float g_proj_raw[BMAX * 4];
__device__ __align__(16) float g_proj[BMAX * 4];
__device__ __align__(16) float g_pn[BMAX * 4];
__device__ float  g_stats[8];
__device__ __align__(16) float g_wp[NJC * BMAX * 4];
__device__ float  g_srow[BMAX];
__device__ float  g_S;

// ================= K1: conv1+relu+pool + conv2+relu+pool (one image / block) =========
// EXACT R10 version (274.5us best). Channel-paired, scalar FMA, padded h1. FROZEN.
__global__ __launch_bounds__(128) void k_conv(
    const float* __restrict__ x, const float* __restrict__ w1, const float* __restrict__ b1,
    const float* __restrict__ w2, const float* __restrict__ b2)
{
    __shared__ __align__(16) float xp[30 * 30];
    __shared__ __align__(16) float h1[8 * H1C];
    __shared__ __align__(16) float sw1[72];
    __shared__ __align__(16) float sw2[1152];
    __shared__ float sb1[8], sb2[16];

    const int img = blockIdx.x;
    const int tid = threadIdx.x;

    for (int i = tid; i < 900; i += 128) xp[i] = 0.f;
    for (int i = tid; i < 8 * H1C; i += 128) h1[i] = 0.f;
    if (tid < 72) sw1[tid] = w1[tid];
    if (tid < 8)  sb1[tid] = b1[tid];
    for (int i = tid; i < 1152; i += 128) sw2[i] = w2[i];
    if (tid < 16) sb2[tid] = b2[tid];
    __syncthreads();

    const float* xi = x + (size_t)img * 784;
    for (int i = tid; i < 784; i += 128) {
        int y = i / 28, xx = i % 28;
        xp[(y + 1) * 30 + (xx + 1)] = xi[i];
    }
    __syncthreads();

    // conv1 (1->8) + relu + pool: thread computes channels (c, c+4) at position p.
    for (int idx = tid; idx < 4 * 196; idx += 128) {
        int c = idx / 196, p = idx % 196;
        int py = p / 14, px = p % 14;
        int y0 = 2 * py, x0 = 2 * px;
        float v[4][4];
        #pragma unroll
        for (int dy = 0; dy < 4; dy++) {
            const float2* rp = (const float2*)(xp + (y0 + dy) * 30 + x0);
            float2 a = rp[0], b = rp[1];
            v[dy][0] = a.x; v[dy][1] = a.y; v[dy][2] = b.x; v[dy][3] = b.y;
        }
        const float* wa = sw1 + c * 9;
        const float* wb = sw1 + (c + 4) * 9;
        float a00 = 0.f, a01 = 0.f, a10 = 0.f, a11 = 0.f;
        float b00 = 0.f, b01 = 0.f, b10 = 0.f, b11 = 0.f;
        #pragma unroll
        for (int dy = 0; dy < 3; dy++)
            #pragma unroll
            for (int dx = 0; dx < 3; dx++) {
                float wwa = wa[dy * 3 + dx];
                float wwb = wb[dy * 3 + dx];
                a00 += wwa * v[dy][dx];
                a01 += wwa * v[dy][dx + 1];
                a10 += wwa * v[dy + 1][dx];
                a11 += wwa * v[dy + 1][dx + 1];
                b00 += wwb * v[dy][dx];
                b01 += wwb * v[dy][dx + 1];
                b10 += wwb * v[dy + 1][dx];
                b11 += wwb * v[dy + 1][dx + 1];
            }
        float ma = fmaxf(fmaxf(a00, a01), fmaxf(a10, a11)) + sb1[c];
        float mb = fmaxf(fmaxf(b00, b01), fmaxf(b10, b11)) + sb1[c + 4];
        h1[c * H1C + (py + 1) * H1S + (px + 1)]       = fmaxf(ma, 0.f);
        h1[(c + 4) * H1C + (py + 1) * H1S + (px + 1)] = fmaxf(mb, 0.f);
    }
    __syncthreads();

    // conv2 (8->16) + relu + pool: thread computes channels (co, co+8) at position p.
    float* fo = g_feat + (size_t)img * 784;
    for (int idx = tid; idx < 8 * 49; idx += 128) {
        int co = idx / 49, p = idx % 49;
        int py = p / 7, px = p % 7;
        int y0 = 2 * py, x0 = 2 * px;
        float a00 = 0.f, a01 = 0.f, a10 = 0.f, a11 = 0.f;
        float b00 = 0.f, b01 = 0.f, b10 = 0.f, b11 = 0.f;
        #pragma unroll
        for (int ci = 0; ci < 8; ci++) {
            const float* wa = sw2 + (co * 8 + ci) * 9;
            const float* wb = sw2 + ((co + 8) * 8 + ci) * 9;
            const float* hb = h1 + ci * H1C;
            float v[4][4];
            #pragma unroll
            for (int dy = 0; dy < 4; dy++) {
                const float2* rp = (const float2*)(hb + (y0 + dy) * H1S + x0);
                float2 a = rp[0], b = rp[1];
                v[dy][0] = a.x; v[dy][1] = a.y; v[dy][2] = b.x; v[dy][3] = b.y;
            }
            #pragma unroll
            for (int dy = 0; dy < 3; dy++)
                #pragma unroll
                for (int dx = 0; dx < 3; dx++) {
                    float wwa = wa[dy * 3 + dx];
                    float wwb = wb[dy * 3 + dx];
                    a00 += wwa * v[dy][dx];
                    a01 += wwa * v[dy][dx + 1];
                    a10 += wwa * v[dy + 1][dx];
                    a11 += wwa * v[dy + 1][dx + 1];
                    b00 += wwb * v[dy][dx];
                    b01 += wwb * v[dy][dx + 1];
                    b10 += wwb * v[dy + 1][dx];
                    b11 += wwb * v[dy + 1][dx + 1];
                }
        }
        float ma = fmaxf(fmaxf(a00, a01), fmaxf(a10, a11)) + sb2[co];
        float mb = fmaxf(fmaxf(b00, b01), fmaxf(b10, b11)) + sb2[co + 8];
        fo[co * 49 + py * 7 + px]       = fmaxf(ma, 0.f);
        fo[(co + 8) * 49 + py * 7 + px] = fmaxf(mb, 0.f);
    }
}

// ================= K2: fc1 (784->64, relu) + fc2 (64->4), 64 images / block ==========
#define KT 56
__global__ __launch_bounds__(256) void k_fc(
    const float* __restrict__ w1, const float* __restrict__ b1,
    const float* __restrict__ w2, const float* __restrict__ b2, int B)
{
    __shared__ float As[64][KT + 1];
    __shared__ float Ws[64][KT + 1];
    __shared__ float Hs[64][65];

    const int i0 = blockIdx.x * 64;
    const int tid = threadIdx.x;
    const int tx = tid & 15, ty = tid >> 4;

    float acc[4][4] = {};

    for (int k0 = 0; k0 < 784; k0 += KT) {
        for (int e = tid; e < 64 * KT; e += 256) {
            int r = e / KT, kk = e - r * KT;
            int row = i0 + r;
            As[r][kk] = (row < B) ? g_feat[(size_t)row * 784 + k0 + kk] : 0.f;
            Ws[r][kk] = w1[r * 784 + k0 + kk];
        }
        __syncthreads();
        #pragma unroll 4
        for (int kk = 0; kk < KT; kk++) {
            float a[4], b[4];
            #pragma unroll
            for (int r = 0; r < 4; r++) a[r] = As[ty * 4 + r][kk];
            #pragma unroll
            for (int c = 0; c < 4; c++) b[c] = Ws[tx * 4 + c][kk];
            #pragma unroll
            for (int r = 0; r < 4; r++)
                #pragma unroll
                for (int c = 0; c < 4; c++)
                    acc[r][c] += a[r] * b[c];
        }
        __syncthreads();
    }

    #pragma unroll
    for (int r = 0; r < 4; r++)
        #pragma unroll
        for (int c = 0; c < 4; c++) {
            int o = tx * 4 + c;
            Hs[ty * 4 + r][o] = fmaxf(acc[r][c] + b1[o], 0.f);
        }
    __syncthreads();

    int m = tid >> 2, c4 = tid & 3;
    if (i0 + m < B) {
        float s = b2[c4];
        #pragma unroll
        for (int o = 0; o < 64; o++) s += w2[c4 * 64 + o] * Hs[m][o];
        g_proj_raw[(size_t)(i0 + m) * 4 + c4] = s;
    }
}

// ================= K3: batchnorm stats (single block) — R10 split version ==========
__global__ __launch_bounds__(1024) void k_bnstats(int B)
{
    __shared__ float red[32][8];
    const int tid = threadIdx.x;
    float s0 = 0, s1 = 0, s2 = 0, s3 = 0, q0 = 0, q1 = 0, q2 = 0, q3 = 0;
    const float4* pr = (const float4*)g_proj_raw;
    for (int i = tid; i < B; i += 1024) {
        float4 v = pr[i];
        s0 += v.x; s1 += v.y; s2 += v.z; s3 += v.w;
        q0 += v.x * v.x; q1 += v.y * v.y; q2 += v.z * v.z; q3 += v.w * v.w;
    }
    #pragma unroll
    for (int o = 16; o > 0; o >>= 1) {
        s0 += __shfl_down_sync(0xffffffffu, s0, o);
        s1 += __shfl_down_sync(0xffffffffu, s1, o);
        s2 += __shfl_down_sync(0xffffffffu, s2, o);
        s3 += __shfl_down_sync(0xffffffffu, s3, o);
        q0 += __shfl_down_sync(0xffffffffu, q0, o);
        q1 += __shfl_down_sync(0xffffffffu, q1, o);
        q2 += __shfl_down_sync(0xffffffffu, q2, o);
        q3 += __shfl_down_sync(0xffffffffu, q3, o);
    }
    int warp = tid >> 5, lane = tid & 31;
    if (lane == 0) {
        red[warp][0] = s0; red[warp][1] = s1; red[warp][2] = s2; red[warp][3] = s3;
        red[warp][4] = q0; red[warp][5] = q1; red[warp][6] = q2; red[warp][7] = q3;
    }
    __syncthreads();
    if (tid < 8) {
        float a = 0.f;
        for (int w = 0; w < 32; w++) a += red[w][tid];
        red[0][tid] = a;
    }
    __syncthreads();
    if (tid < 4) {
        float invB = 1.f / (float)B;
        float mean = red[0][tid] * invB;
        float var  = red[0][4 + tid] * invB - mean * mean;
        g_stats[tid] = mean;
        g_stats[4 + tid] = rsqrtf(var + 1e-5f);
    }
    if (tid == 0) g_S = 0.f;
}

// ================= K4: apply BN + row-normalize — R10 split version ==========
__global__ __launch_bounds__(256) void k_bnapply(
    const float* __restrict__ gamma, const float* __restrict__ beta, int B)
{
    int i = blockIdx.x * 256 + threadIdx.x;
    if (i >= B) return;
    float4 v = ((const float4*)g_proj_raw)[i];
    float p0 = (v.x - g_stats[0]) * g_stats[4] * gamma[0] + beta[0];
    float p1 = (v.y - g_stats[1]) * g_stats[5] * gamma[1] + beta[1];
    float p2 = (v.z - g_stats[2]) * g_stats[6] * gamma[2] + beta[2];
    float p3 = (v.w - g_stats[3]) * g_stats[7] * gamma[3] + beta[3];
    float inv = 1.f / (sqrtf(p0 * p0 + p1 * p1 + p2 * p2 + p3 * p3) + 1e-12f);
    ((float4*)g_proj)[i] = make_float4(p0, p1, p2, p3);
    ((float4*)g_pn)[i]   = make_float4(p0 * inv, p1 * inv, p2 * inv, p3 * inv);
}

// ================= K5: pairwise adjacency-weighted sum =================
// 4 i-rows / thread; NJC=64 -> 1024 blocks (occupancy was the binding term at 512).
// Predicated accumulate (w += pj under the compare) is bit-exact vs select+fma:
// fmaf(1,pj,w)=rn(pj+w)=FADD, fmaf(0,pj,w)=w. Self-pair subtracted in k_combine.
#define TJ 256
__global__ __launch_bounds__(IT) void k_pair(int B)
{
    __shared__ float4 pns[TJ];
    __shared__ float4 prs[TJ];
    const int tid = threadIdx.x;
    const int ib  = blockIdx.x * (4 * IT);
    const int jc  = blockIdx.y;
    const int chunk = (B + NJC - 1) / NJC;
    const int jbeg = jc * chunk;
    const int jend = min(jbeg + chunk, B);

    const float4* pn   = (const float4*)g_pn;
    const float4* proj = (const float4*)g_proj;

    float4 v[4];
    int    idx[4];
    #pragma unroll
    for (int r = 0; r < 4; r++) {
        idx[r] = ib + r * IT + tid;
        v[r] = (idx[r] < B) ? pn[idx[r]] : make_float4(0.f, 0.f, 0.f, 0.f);
    }
    float w0[4] = {}, w1[4] = {}, w2[4] = {}, w3[4] = {};

    for (int jb = jbeg; jb < jend; jb += TJ) {
        int n = jend - jb;
        for (int t = tid; t < TJ; t += IT) {
            if (t < n) { pns[t] = pn[jb + t]; prs[t] = proj[jb + t]; }
            else       { pns[t] = make_float4(0.f, 0.f, 0.f, 0.f);
                         prs[t] = make_float4(0.f, 0.f, 0.f, 0.f); }
        }
        __syncthreads();
        #pragma unroll 4
        for (int jj = 0; jj < TJ; jj++) {
            float4 q  = pns[jj];
            float4 pj = prs[jj];
            #pragma unroll
            for (int r = 0; r < 4; r++) {
                float d = v[r].x * q.x + v[r].y * q.y + v[r].z * q.z + v[r].w * q.w;
                if (d * d >= 0.9f) {
                    w0[r] += pj.x; w1[r] += pj.y; w2[r] += pj.z; w3[r] += pj.w;
                }
            }
        }
        __syncthreads();
    }
    float4* wp = (float4*)g_wp;
    #pragma unroll
    for (int r = 0; r < 4; r++)
        if (idx[r] < B)
            wp[(size_t)jc * B + idx[r]] = make_float4(w0[r], w1[r], w2[r], w3[r]);
}

// ================= K6: combine partials (subtract self), row sums, diff^2 ==========
__global__ __launch_bounds__(256) void k_combine(int B)
{
    int i = blockIdx.x * 256 + threadIdx.x;
    float ds = 0.f;
    if (i < B) {
        const float4* wpp = (const float4*)g_wp;
        float4 w = wpp[i];
        #pragma unroll
        for (int jc = 1; jc < NJC; jc++) {
            float4 t = wpp[(size_t)jc * B + i];
            w.x += t.x; w.y += t.y; w.z += t.z; w.w += t.w;
        }
        float4 p = ((const float4*)g_proj)[i];
        // subtract self-pair contribution (off-diagonal mask in reference)
        w.x -= p.x; w.y -= p.y; w.z -= p.z; w.w -= p.w;
        g_srow[i] = p.x + p.y + p.z + p.w + w.x + w.y + w.z + w.w;
        float d0 = p.x - w.x, d1 = p.y - w.y, d2 = p.z - w.z, d3 = p.w - w.w;
        ds = d0 * d0 + d1 * d1 + d2 * d2 + d3 * d3;
    }
    #pragma unroll
    for (int o = 16; o > 0; o >>= 1) ds += __shfl_down_sync(0xffffffffu, ds, o);
    __shared__ float red[8];
    int warp = threadIdx.x >> 5, lane = threadIdx.x & 31;
    if (lane == 0) red[warp] = ds;
    __syncthreads();
    if (threadIdx.x == 0) {
        float t = 0.f;
        #pragma unroll
        for (int w = 0; w < 8; w++) t += red[w];
        atomicAdd(&g_S, t);
    }
}

// ================= K7: kernel value + sigmoid epilogue =================
__global__ __launch_bounds__(256) void k_final(float* __restrict__ out, int B)
{
    int i = blockIdx.x * 256 + threadIdx.x;
    if (i >= B) return;
    float kv = expf(-g_S);              // GAMMA = 1
    float logit = g_srow[i] + kv;       // SHIFT = 0
    float p = 1.f / (1.f + expf(-logit));
    out[2 * i]     = p;
    out[2 * i + 1] = 1.f - p;
}

// ================= launcher =================
extern "C" void kernel_launch(void* const* d_in, const int* in_sizes, int n_in,
                              void* d_out, int out_size)
{
    const float* x   = (const float*)d_in[0];
    const float* c1w = (const float*)d_in[1];
    const float* c1b = (const float*)d_in[2];
    const float* c2w = (const float*)d_in[3];
    const float* c2b = (const float*)d_in[4];
    const float* f1w = (const float*)d_in[5];
    const float* f1b = (const float*)d_in[6];
    const float* f2w = (const float*)d_in[7];
    const float* f2b = (const float*)d_in[8];
    const float* gam = (const float*)d_in[9];
    const float* bet = (const float*)d_in[10];
    float* out = (float*)d_out;

    const int B = in_sizes[0] / 784;

    k_conv<<<B, 128>>>(x, c1w, c1b, c2w, c2b);
    k_fc<<<(B + 63) / 64, 256>>>(f1w, f1b, f2w, f2b, B);
    k_bnstats<<<1, 1024>>>(B);
    k_bnapply<<<(B + 255) / 256, 256>>>(gam, bet, B);
    dim3 gp((B + 4 * IT - 1) / (4 * IT), NJC);
    k_pair<<<gp, IT>>>(B);
    k_combine<<<(B + 255) / 256, 256>>>(B);
    k_final<<<(B + 255) / 256, 256>>>(out, B);
}

// round 14
// speedup vs baseline: 1.0655x; 1.0655x over previous
#include <cuda_runtime.h>
#include <math.h>

#define BMAX 8192
#define NJC 64
#define IT 128
#define TJ 128

// h1 padded layout (R8 win): row stride 22, channel stride 352.
#define H1S 22
#define H1C 352

// ---------------- scratch (device globals: no allocation allowed) ----------------
__device__ float  g_feat[BMAX * 784];
__device__ __align__(16) float g_proj_raw[BMAX * 4];
__device__ __align__(16) float g_proj[BMAX * 4];
__device__ __align__(16) float g_pn[BMAX * 4];
__device__ float  g_stats[8];
__device__ __align__(16) float g_wp[NJC * BMAX * 4];
__device__ float  g_srow[BMAX];
__device__ float  g_S;

// ================= K1: conv1+relu+pool + conv2+relu+pool (one image / block) =========
// EXACT R10 version (274.5us best). Channel-paired, scalar FMA, padded h1. FROZEN.
__global__ __launch_bounds__(128) void k_conv(
    const float* __restrict__ x, const float* __restrict__ w1, const float* __restrict__ b1,
    const float* __restrict__ w2, const float* __restrict__ b2)
{
    __shared__ __align__(16) float xp[30 * 30];
    __shared__ __align__(16) float h1[8 * H1C];
    __shared__ __align__(16) float sw1[72];
    __shared__ __align__(16) float sw2[1152];
    __shared__ float sb1[8], sb2[16];

    const int img = blockIdx.x;
    const int tid = threadIdx.x;

    for (int i = tid; i < 900; i += 128) xp[i] = 0.f;
    for (int i = tid; i < 8 * H1C; i += 128) h1[i] = 0.f;
    if (tid < 72) sw1[tid] = w1[tid];
    if (tid < 8)  sb1[tid] = b1[tid];
    for (int i = tid; i < 1152; i += 128) sw2[i] = w2[i];
    if (tid < 16) sb2[tid] = b2[tid];
    __syncthreads();

    const float* xi = x + (size_t)img * 784;
    for (int i = tid; i < 784; i += 128) {
        int y = i / 28, xx = i % 28;
        xp[(y + 1) * 30 + (xx + 1)] = xi[i];
    }
    __syncthreads();

    // conv1 (1->8) + relu + pool: thread computes channels (c, c+4) at position p.
    for (int idx = tid; idx < 4 * 196; idx += 128) {
        int c = idx / 196, p = idx % 196;
        int py = p / 14, px = p % 14;
        int y0 = 2 * py, x0 = 2 * px;
        float v[4][4];
        #pragma unroll
        for (int dy = 0; dy < 4; dy++) {
            const float2* rp = (const float2*)(xp + (y0 + dy) * 30 + x0);
            float2 a = rp[0], b = rp[1];
            v[dy][0] = a.x; v[dy][1] = a.y; v[dy][2] = b.x; v[dy][3] = b.y;
        }
        const float* wa = sw1 + c * 9;
        const float* wb = sw1 + (c + 4) * 9;
        float a00 = 0.f, a01 = 0.f, a10 = 0.f, a11 = 0.f;
        float b00 = 0.f, b01 = 0.f, b10 = 0.f, b11 = 0.f;
        #pragma unroll
        for (int dy = 0; dy < 3; dy++)
            #pragma unroll
            for (int dx = 0; dx < 3; dx++) {
                float wwa = wa[dy * 3 + dx];
                float wwb = wb[dy * 3 + dx];
                a00 += wwa * v[dy][dx];
                a01 += wwa * v[dy][dx + 1];
                a10 += wwa * v[dy + 1][dx];
                a11 += wwa * v[dy + 1][dx + 1];
                b00 += wwb * v[dy][dx];
                b01 += wwb * v[dy][dx + 1];
                b10 += wwb * v[dy + 1][dx];
                b11 += wwb * v[dy + 1][dx + 1];
            }
        float ma = fmaxf(fmaxf(a00, a01), fmaxf(a10, a11)) + sb1[c];
        float mb = fmaxf(fmaxf(b00, b01), fmaxf(b10, b11)) + sb1[c + 4];
        h1[c * H1C + (py + 1) * H1S + (px + 1)]       = fmaxf(ma, 0.f);
        h1[(c + 4) * H1C + (py + 1) * H1S + (px + 1)] = fmaxf(mb, 0.f);
    }
    __syncthreads();

    // conv2 (8->16) + relu + pool: thread computes channels (co, co+8) at position p.
    float* fo = g_feat + (size_t)img * 784;
    for (int idx = tid; idx < 8 * 49; idx += 128) {
        int co = idx / 49, p = idx % 49;
        int py = p / 7, px = p % 7;
        int y0 = 2 * py, x0 = 2 * px;
        float a00 = 0.f, a01 = 0.f, a10 = 0.f, a11 = 0.f;
        float b00 = 0.f, b01 = 0.f, b10 = 0.f, b11 = 0.f;
        #pragma unroll
        for (int ci = 0; ci < 8; ci++) {
            const float* wa = sw2 + (co * 8 + ci) * 9;
            const float* wb = sw2 + ((co + 8) * 8 + ci) * 9;
            const float* hb = h1 + ci * H1C;
            float v[4][4];
            #pragma unroll
            for (int dy = 0; dy < 4; dy++) {
                const float2* rp = (const float2*)(hb + (y0 + dy) * H1S + x0);
                float2 a = rp[0], b = rp[1];
                v[dy][0] = a.x; v[dy][1] = a.y; v[dy][2] = b.x; v[dy][3] = b.y;
            }
            #pragma unroll
            for (int dy = 0; dy < 3; dy++)
                #pragma unroll
                for (int dx = 0; dx < 3; dx++) {
                    float wwa = wa[dy * 3 + dx];
                    float wwb = wb[dy * 3 + dx];
                    a00 += wwa * v[dy][dx];
                    a01 += wwa * v[dy][dx + 1];
                    a10 += wwa * v[dy + 1][dx];
                    a11 += wwa * v[dy + 1][dx + 1];
                    b00 += wwb * v[dy][dx];
                    b01 += wwb * v[dy][dx + 1];
                    b10 += wwb * v[dy + 1][dx];
                    b11 += wwb * v[dy + 1][dx + 1];
                }
        }
        float ma = fmaxf(fmaxf(a00, a01), fmaxf(a10, a11)) + sb2[co];
        float mb = fmaxf(fmaxf(b00, b01), fmaxf(b10, b11)) + sb2[co + 8];
        fo[co * 49 + py * 7 + px]       = fmaxf(ma, 0.f);
        fo[(co + 8) * 49 + py * 7 + px] = fmaxf(mb, 0.f);
    }
}

// ================= K2: fc1 (784->64, relu) + fc2 (64->4), 64 images / block ==========
#define KT 56
__global__ __launch_bounds__(256) void k_fc(
    const float* __restrict__ w1, const float* __restrict__ b1,
    const float* __restrict__ w2, const float* __restrict__ b2, int B)
{
    __shared__ float As[64][KT + 1];
    __shared__ float Ws[64][KT + 1];
    __shared__ float Hs[64][65];

    const int i0 = blockIdx.x * 64;
    const int tid = threadIdx.x;
    const int tx = tid & 15, ty = tid >> 4;

    float acc[4][4] = {};

    for (int k0 = 0; k0 < 784; k0 += KT) {
        for (int e = tid; e < 64 * KT; e += 256) {
            int r = e / KT, kk = e - r * KT;
            int row = i0 + r;
            As[r][kk] = (row < B) ? g_feat[(size_t)row * 784 + k0 + kk] : 0.f;
            Ws[r][kk] = w1[r * 784 + k0 + kk];
        }
        __syncthreads();
        #pragma unroll 4
        for (int kk = 0; kk < KT; kk++) {
            float a[4], b[4];
            #pragma unroll
            for (int r = 0; r < 4; r++) a[r] = As[ty * 4 + r][kk];
            #pragma unroll
            for (int c = 0; c < 4; c++) b[c] = Ws[tx * 4 + c][kk];
            #pragma unroll
            for (int r = 0; r < 4; r++)
                #pragma unroll
                for (int c = 0; c < 4; c++)
                    acc[r][c] += a[r] * b[c];
        }
        __syncthreads();
    }

    #pragma unroll
    for (int r = 0; r < 4; r++)
        #pragma unroll
        for (int c = 0; c < 4; c++) {
            int o = tx * 4 + c;
            Hs[ty * 4 + r][o] = fmaxf(acc[r][c] + b1[o], 0.f);
        }
    __syncthreads();

    int m = tid >> 2, c4 = tid & 3;
    if (i0 + m < B) {
        float s = b2[c4];
        #pragma unroll
        for (int o = 0; o < 64; o++) s += w2[c4 * 64 + o] * Hs[m][o];
        g_proj_raw[(size_t)(i0 + m) * 4 + c4] = s;
    }
}

// ================= K3: batchnorm stats (single block) =================
__global__ __launch_bounds__(1024) void k_bnstats(int B)
{
    __shared__ float red[32][8];
    const int tid = threadIdx.x;
    float s0 = 0, s1 = 0, s2 = 0, s3 = 0, q0 = 0, q1 = 0, q2 = 0, q3 = 0;
    const float4* pr = (const float4*)g_proj_raw;
    for (int i = tid; i < B; i += 1024) {
        float4 v = pr[i];
        s0 += v.x; s1 += v.y; s2 += v.z; s3 += v.w;
        q0 += v.x * v.x; q1 += v.y * v.y; q2 += v.z * v.z; q3 += v.w * v.w;
    }
    #pragma unroll
    for (int o = 16; o > 0; o >>= 1) {
        s0 += __shfl_down_sync(0xffffffffu, s0, o);
        s1 += __shfl_down_sync(0xffffffffu, s1, o);
        s2 += __shfl_down_sync(0xffffffffu, s2, o);
        s3 += __shfl_down_sync(0xffffffffu, s3, o);
        q0 += __shfl_down_sync(0xffffffffu, q0, o);
        q1 += __shfl_down_sync(0xffffffffu, q1, o);
        q2 += __shfl_down_sync(0xffffffffu, q2, o);
        q3 += __shfl_down_sync(0xffffffffu, q3, o);
    }
    int warp = tid >> 5, lane = tid & 31;
    if (lane == 0) {
        red[warp][0] = s0; red[warp][1] = s1; red[warp][2] = s2; red[warp][3] = s3;
        red[warp][4] = q0; red[warp][5] = q1; red[warp][6] = q2; red[warp][7] = q3;
    }
    __syncthreads();
    if (tid < 8) {
        float a = 0.f;
        for (int w = 0; w < 32; w++) a += red[w][tid];
        red[0][tid] = a;
    }
    __syncthreads();
    if (tid < 4) {
        float invB = 1.f / (float)B;
        float mean = red[0][tid] * invB;
        float var  = red[0][4 + tid] * invB - mean * mean;
        g_stats[tid] = mean;
        g_stats[4 + tid] = rsqrtf(var + 1e-5f);
    }
    if (tid == 0) g_S = 0.f;
}

// ================= K4: apply BN + row-normalize =================
__global__ __launch_bounds__(256) void k_bnapply(
    const float* __restrict__ gamma, const float* __restrict__ beta, int B)
{
    int i = blockIdx.x * 256 + threadIdx.x;
    if (i >= B) return;
    float4 v = ((const float4*)g_proj_raw)[i];
    float p0 = (v.x - g_stats[0]) * g_stats[4] * gamma[0] + beta[0];
    float p1 = (v.y - g_stats[1]) * g_stats[5] * gamma[1] + beta[1];
    float p2 = (v.z - g_stats[2]) * g_stats[6] * gamma[2] + beta[2];
    float p3 = (v.w - g_stats[3]) * g_stats[7] * gamma[3] + beta[3];
    float inv = 1.f / (sqrtf(p0 * p0 + p1 * p1 + p2 * p2 + p3 * p3) + 1e-12f);
    ((float4*)g_proj)[i] = make_float4(p0, p1, p2, p3);
    ((float4*)g_pn)[i]   = make_float4(p0 * inv, p1 * inv, p2 * inv, p3 * inv);
}

// ================= K5: pairwise adjacency-weighted sum =================
// 4 i-rows / thread, select+fma inner loop (R10-proven, no divergence).
// NJC=64 with TJ=128: chunk exactly fills the tile (no zero-padding waste),
// 1024 blocks -> ~2x occupancy vs R10's 512. Self-pair subtracted in k_combine.
__global__ __launch_bounds__(IT) void k_pair(int B)
{
    __shared__ float4 pns[TJ];
    __shared__ float4 prs[TJ];
    const int tid = threadIdx.x;
    const int ib  = blockIdx.x * (4 * IT);
    const int jc  = blockIdx.y;
    const int chunk = (B + NJC - 1) / NJC;
    const int jbeg = jc * chunk;
    const int jend = min(jbeg + chunk, B);

    const float4* pn   = (const float4*)g_pn;
    const float4* proj = (const float4*)g_proj;

    float4 v[4];
    int    idx[4];
    #pragma unroll
    for (int r = 0; r < 4; r++) {
        idx[r] = ib + r * IT + tid;
        v[r] = (idx[r] < B) ? pn[idx[r]] : make_float4(0.f, 0.f, 0.f, 0.f);
    }
    float w0[4] = {}, w1[4] = {}, w2[4] = {}, w3[4] = {};

    for (int jb = jbeg; jb < jend; jb += TJ) {
        int n = jend - jb;
        for (int t = tid; t < TJ; t += IT) {
            if (t < n) { pns[t] = pn[jb + t]; prs[t] = proj[jb + t]; }
            else       { pns[t] = make_float4(0.f, 0.f, 0.f, 0.f);
                         prs[t] = make_float4(0.f, 0.f, 0.f, 0.f); }
        }
        __syncthreads();
        #pragma unroll 4
        for (int jj = 0; jj < TJ; jj++) {
            float4 q  = pns[jj];
            float4 pj = prs[jj];
            #pragma unroll
            for (int r = 0; r < 4; r++) {
                float d = v[r].x * q.x + v[r].y * q.y + v[r].z * q.z + v[r].w * q.w;
                float s = (d * d >= 0.9f) ? 1.f : 0.f;
                w0[r] = fmaf(s, pj.x, w0[r]); w1[r] = fmaf(s, pj.y, w1[r]);
                w2[r] = fmaf(s, pj.z, w2[r]); w3[r] = fmaf(s, pj.w, w3[r]);
            }
        }
        __syncthreads();
    }
    float4* wp = (float4*)g_wp;
    #pragma unroll
    for (int r = 0; r < 4; r++)
        if (idx[r] < B)
            wp[(size_t)jc * B + idx[r]] = make_float4(w0[r], w1[r], w2[r], w3[r]);
}

// ================= K6: combine partials (subtract self), row sums, diff^2 ==========
__global__ __launch_bounds__(256) void k_combine(int B)
{
    int i = blockIdx.x * 256 + threadIdx.x;
    float ds = 0.f;
    if (i < B) {
        const float4* wpp = (const float4*)g_wp;
        float4 w = wpp[i];
        #pragma unroll
        for (int jc = 1; jc < NJC; jc++) {
            float4 t = wpp[(size_t)jc * B + i];
            w.x += t.x; w.y += t.y; w.z += t.z; w.w += t.w;
        }
        float4 p = ((const float4*)g_proj)[i];
        // subtract self-pair contribution (off-diagonal mask in reference)
        w.x -= p.x; w.y -= p.y; w.z -= p.z; w.w -= p.w;
        g_srow[i] = p.x + p.y + p.z + p.w + w.x + w.y + w.z + w.w;
        float d0 = p.x - w.x, d1 = p.y - w.y, d2 = p.z - w.z, d3 = p.w - w.w;
        ds = d0 * d0 + d1 * d1 + d2 * d2 + d3 * d3;
    }
    #pragma unroll
    for (int o = 16; o > 0; o >>= 1) ds += __shfl_down_sync(0xffffffffu, ds, o);
    __shared__ float red[8];
    int warp = threadIdx.x >> 5, lane = threadIdx.x & 31;
    if (lane == 0) red[warp] = ds;
    __syncthreads();
    if (threadIdx.x == 0) {
        float t = 0.f;
        #pragma unroll
        for (int w = 0; w < 8; w++) t += red[w];
        atomicAdd(&g_S, t);
    }
}

// ================= K7: kernel value + sigmoid epilogue =================
__global__ __launch_bounds__(256) void k_final(float* __restrict__ out, int B)
{
    int i = blockIdx.x * 256 + threadIdx.x;
    if (i >= B) return;
    float kv = expf(-g_S);              // GAMMA = 1
    float logit = g_srow[i] + kv;       // SHIFT = 0
    float p = 1.f / (1.f + expf(-logit));
    out[2 * i]     = p;
    out[2 * i + 1] = 1.f - p;
}

// ================= launcher =================
extern "C" void kernel_launch(void* const* d_in, const int* in_sizes, int n_in,
                              void* d_out, int out_size)
{
    const float* x   = (const float*)d_in[0];
    const float* c1w = (const float*)d_in[1];
    const float* c1b = (const float*)d_in[2];
    const float* c2w = (const float*)d_in[3];
    const float* c2b = (const float*)d_in[4];
    const float* f1w = (const float*)d_in[5];
    const float* f1b = (const float*)d_in[6];
    const float* f2w = (const float*)d_in[7];
    const float* f2b = (const float*)d_in[8];
    const float* gam = (const float*)d_in[9];
    const float* bet = (const float*)d_in[10];
    float* out = (float*)d_out;

    const int B = in_sizes[0] / 784;

    k_conv<<<B, 128>>>(x, c1w, c1b, c2w, c2b);
    k_fc<<<(B + 63) / 64, 256>>>(f1w, f1b, f2w, f2b, B);
    k_bnstats<<<1, 1024>>>(B);
    k_bnapply<<<(B + 255) / 256, 256>>>(gam, bet, B);
    dim3 gp((B + 4 * IT - 1) / (4 * IT), NJC);
    k_pair<<<gp, IT>>>(B);
    k_combine<<<(B + 255) / 256, 256>>>(B);
    k_final<<<(B + 255) / 256, 256>>>(out, B);
}

// round 15
// speedup vs baseline: 1.0742x; 1.0082x over previous
#include <cuda_runtime.h>
#include <math.h>

#define BMAX 8192
#define NJC 64
#define IT 128
#define TJ 128

// h1 padded layout (R8 win): row stride 22, channel stride 352.
#define H1S 22
#define H1C 352

// ---------------- scratch (device globals: no allocation allowed) ----------------
__device__ float  g_feat[BMAX * 784];
__device__ __align__(16) float g_proj_raw[BMAX * 4];
__device__ __align__(16) float g_proj[BMAX * 4];
__device__ __align__(16) float g_pn[BMAX * 4];
__device__ float  g_stats[8];
__device__ __align__(16) float g_wp[NJC * BMAX * 4];
__device__ float  g_srow[BMAX];
__device__ float  g_S;

// ================= K1: conv1+relu+pool + conv2+relu+pool (one image / block) =========
// R10 compute (frozen, bit-exact). Setup slimmed: border-only zeroing (the interiors
// are fully overwritten before being read) and a single setup barrier.
__global__ __launch_bounds__(128) void k_conv(
    const float* __restrict__ x, const float* __restrict__ w1, const float* __restrict__ b1,
    const float* __restrict__ w2, const float* __restrict__ b2)
{
    __shared__ __align__(16) float xp[30 * 30];
    __shared__ __align__(16) float h1[8 * H1C];
    __shared__ __align__(16) float sw1[72];
    __shared__ __align__(16) float sw2[1152];
    __shared__ float sb1[8], sb2[16];

    const int img = blockIdx.x;
    const int tid = threadIdx.x;

    // --- setup phase (one barrier): halo zeroing + weights + image interior ---
    // xp border: rows 0,29 (30 each) + cols 0,29 of rows 1..28 (28 each) = 116
    if (tid < 116) {
        int r, c;
        if (tid < 30)      { r = 0;  c = tid; }
        else if (tid < 60) { r = 29; c = tid - 30; }
        else if (tid < 88) { r = tid - 60 + 1; c = 0; }
        else               { r = tid - 88 + 1; c = 29; }
        xp[r * 30 + c] = 0.f;
    }
    // h1 border ring per channel: rows 0,15 (16 each) + cols 0,15 of rows 1..14 (14 each) = 60
    for (int i = tid; i < 8 * 60; i += 128) {
        int ch = i / 60, e = i - ch * 60;
        int r, c;
        if (e < 16)      { r = 0;  c = e; }
        else if (e < 32) { r = 15; c = e - 16; }
        else if (e < 46) { r = e - 32 + 1; c = 0; }
        else             { r = e - 46 + 1; c = 15; }
        h1[ch * H1C + r * H1S + c] = 0.f;
    }
    if (tid < 72) sw1[tid] = w1[tid];
    if (tid < 8)  sb1[tid] = b1[tid];
    for (int i = tid; i < 1152; i += 128) sw2[i] = w2[i];
    if (tid < 16) sb2[tid] = b2[tid];
    const float* xi = x + (size_t)img * 784;
    for (int i = tid; i < 784; i += 128) {
        int y = i / 28, xx = i % 28;
        xp[(y + 1) * 30 + (xx + 1)] = xi[i];
    }
    __syncthreads();

    // conv1 (1->8) + relu + pool: thread computes channels (c, c+4) at position p.
    for (int idx = tid; idx < 4 * 196; idx += 128) {
        int c = idx / 196, p = idx % 196;
        int py = p / 14, px = p % 14;
        int y0 = 2 * py, x0 = 2 * px;
        float v[4][4];
        #pragma unroll
        for (int dy = 0; dy < 4; dy++) {
            const float2* rp = (const float2*)(xp + (y0 + dy) * 30 + x0);
            float2 a = rp[0], b = rp[1];
            v[dy][0] = a.x; v[dy][1] = a.y; v[dy][2] = b.x; v[dy][3] = b.y;
        }
        const float* wa = sw1 + c * 9;
        const float* wb = sw1 + (c + 4) * 9;
        float a00 = 0.f, a01 = 0.f, a10 = 0.f, a11 = 0.f;
        float b00 = 0.f, b01 = 0.f, b10 = 0.f, b11 = 0.f;
        #pragma unroll
        for (int dy = 0; dy < 3; dy++)
            #pragma unroll
            for (int dx = 0; dx < 3; dx++) {
                float wwa = wa[dy * 3 + dx];
                float wwb = wb[dy * 3 + dx];
                a00 += wwa * v[dy][dx];
                a01 += wwa * v[dy][dx + 1];
                a10 += wwa * v[dy + 1][dx];
                a11 += wwa * v[dy + 1][dx + 1];
                b00 += wwb * v[dy][dx];
                b01 += wwb * v[dy][dx + 1];
                b10 += wwb * v[dy + 1][dx];
                b11 += wwb * v[dy + 1][dx + 1];
            }
        float ma = fmaxf(fmaxf(a00, a01), fmaxf(a10, a11)) + sb1[c];
        float mb = fmaxf(fmaxf(b00, b01), fmaxf(b10, b11)) + sb1[c + 4];
        h1[c * H1C + (py + 1) * H1S + (px + 1)]       = fmaxf(ma, 0.f);
        h1[(c + 4) * H1C + (py + 1) * H1S + (px + 1)] = fmaxf(mb, 0.f);
    }
    __syncthreads();

    // conv2 (8->16) + relu + pool: thread computes channels (co, co+8) at position p.
    float* fo = g_feat + (size_t)img * 784;
    for (int idx = tid; idx < 8 * 49; idx += 128) {
        int co = idx / 49, p = idx % 49;
        int py = p / 7, px = p % 7;
        int y0 = 2 * py, x0 = 2 * px;
        float a00 = 0.f, a01 = 0.f, a10 = 0.f, a11 = 0.f;
        float b00 = 0.f, b01 = 0.f, b10 = 0.f, b11 = 0.f;
        #pragma unroll
        for (int ci = 0; ci < 8; ci++) {
            const float* wa = sw2 + (co * 8 + ci) * 9;
            const float* wb = sw2 + ((co + 8) * 8 + ci) * 9;
            const float* hb = h1 + ci * H1C;
            float v[4][4];
            #pragma unroll
            for (int dy = 0; dy < 4; dy++) {
                const float2* rp = (const float2*)(hb + (y0 + dy) * H1S + x0);
                float2 a = rp[0], b = rp[1];
                v[dy][0] = a.x; v[dy][1] = a.y; v[dy][2] = b.x; v[dy][3] = b.y;
            }
            #pragma unroll
            for (int dy = 0; dy < 3; dy++)
                #pragma unroll
                for (int dx = 0; dx < 3; dx++) {
                    float wwa = wa[dy * 3 + dx];
                    float wwb = wb[dy * 3 + dx];
                    a00 += wwa * v[dy][dx];
                    a01 += wwa * v[dy][dx + 1];
                    a10 += wwa * v[dy + 1][dx];
                    a11 += wwa * v[dy + 1][dx + 1];
                    b00 += wwb * v[dy][dx];
                    b01 += wwb * v[dy][dx + 1];
                    b10 += wwb * v[dy + 1][dx];
                    b11 += wwb * v[dy + 1][dx + 1];
                }
        }
        float ma = fmaxf(fmaxf(a00, a01), fmaxf(a10, a11)) + sb2[co];
        float mb = fmaxf(fmaxf(b00, b01), fmaxf(b10, b11)) + sb2[co + 8];
        fo[co * 49 + py * 7 + px]       = fmaxf(ma, 0.f);
        fo[(co + 8) * 49 + py * 7 + px] = fmaxf(mb, 0.f);
    }
}

// ================= K2: fc1 (784->64, relu) + fc2 (64->4), 64 images / block ==========
#define KT 56
__global__ __launch_bounds__(256) void k_fc(
    const float* __restrict__ w1, const float* __restrict__ b1,
    const float* __restrict__ w2, const float* __restrict__ b2, int B)
{
    __shared__ float As[64][KT + 1];
    __shared__ float Ws[64][KT + 1];
    __shared__ float Hs[64][65];

    const int i0 = blockIdx.x * 64;
    const int tid = threadIdx.x;
    const int tx = tid & 15, ty = tid >> 4;

    float acc[4][4] = {};

    for (int k0 = 0; k0 < 784; k0 += KT) {
        for (int e = tid; e < 64 * KT; e += 256) {
            int r = e / KT, kk = e - r * KT;
            int row = i0 + r;
            As[r][kk] = (row < B) ? g_feat[(size_t)row * 784 + k0 + kk] : 0.f;
            Ws[r][kk] = w1[r * 784 + k0 + kk];
        }
        __syncthreads();
        #pragma unroll 4
        for (int kk = 0; kk < KT; kk++) {
            float a[4], b[4];
            #pragma unroll
            for (int r = 0; r < 4; r++) a[r] = As[ty * 4 + r][kk];
            #pragma unroll
            for (int c = 0; c < 4; c++) b[c] = Ws[tx * 4 + c][kk];
            #pragma unroll
            for (int r = 0; r < 4; r++)
                #pragma unroll
                for (int c = 0; c < 4; c++)
                    acc[r][c] += a[r] * b[c];
        }
        __syncthreads();
    }

    #pragma unroll
    for (int r = 0; r < 4; r++)
        #pragma unroll
        for (int c = 0; c < 4; c++) {
            int o = tx * 4 + c;
            Hs[ty * 4 + r][o] = fmaxf(acc[r][c] + b1[o], 0.f);
        }
    __syncthreads();

    int m = tid >> 2, c4 = tid & 3;
    if (i0 + m < B) {
        float s = b2[c4];
        #pragma unroll
        for (int o = 0; o < 64; o++) s += w2[c4 * 64 + o] * Hs[m][o];
        g_proj_raw[(size_t)(i0 + m) * 4 + c4] = s;
    }
}

// ================= K3: batchnorm stats (single block) =================
__global__ __launch_bounds__(1024) void k_bnstats(int B)
{
    __shared__ float red[32][8];
    const int tid = threadIdx.x;
    float s0 = 0, s1 = 0, s2 = 0, s3 = 0, q0 = 0, q1 = 0, q2 = 0, q3 = 0;
    const float4* pr = (const float4*)g_proj_raw;
    for (int i = tid; i < B; i += 1024) {
        float4 v = pr[i];
        s0 += v.x; s1 += v.y; s2 += v.z; s3 += v.w;
        q0 += v.x * v.x; q1 += v.y * v.y; q2 += v.z * v.z; q3 += v.w * v.w;
    }
    #pragma unroll
    for (int o = 16; o > 0; o >>= 1) {
        s0 += __shfl_down_sync(0xffffffffu, s0, o);
        s1 += __shfl_down_sync(0xffffffffu, s1, o);
        s2 += __shfl_down_sync(0xffffffffu, s2, o);
        s3 += __shfl_down_sync(0xffffffffu, s3, o);
        q0 += __shfl_down_sync(0xffffffffu, q0, o);
        q1 += __shfl_down_sync(0xffffffffu, q1, o);
        q2 += __shfl_down_sync(0xffffffffu, q2, o);
        q3 += __shfl_down_sync(0xffffffffu, q3, o);
    }
    int warp = tid >> 5, lane = tid & 31;
    if (lane == 0) {
        red[warp][0] = s0; red[warp][1] = s1; red[warp][2] = s2; red[warp][3] = s3;
        red[warp][4] = q0; red[warp][5] = q1; red[warp][6] = q2; red[warp][7] = q3;
    }
    __syncthreads();
    if (tid < 8) {
        float a = 0.f;
        for (int w = 0; w < 32; w++) a += red[w][tid];
        red[0][tid] = a;
    }
    __syncthreads();
    if (tid < 4) {
        float invB = 1.f / (float)B;
        float mean = red[0][tid] * invB;
        float var  = red[0][4 + tid] * invB - mean * mean;
        g_stats[tid] = mean;
        g_stats[4 + tid] = rsqrtf(var + 1e-5f);
    }
    if (tid == 0) g_S = 0.f;
}

// ================= K4: apply BN + row-normalize =================
__global__ __launch_bounds__(256) void k_bnapply(
    const float* __restrict__ gamma, const float* __restrict__ beta, int B)
{
    int i = blockIdx.x * 256 + threadIdx.x;
    if (i >= B) return;
    float4 v = ((const float4*)g_proj_raw)[i];
    float p0 = (v.x - g_stats[0]) * g_stats[4] * gamma[0] + beta[0];
    float p1 = (v.y - g_stats[1]) * g_stats[5] * gamma[1] + beta[1];
    float p2 = (v.z - g_stats[2]) * g_stats[6] * gamma[2] + beta[2];
    float p3 = (v.w - g_stats[3]) * g_stats[7] * gamma[3] + beta[3];
    float inv = 1.f / (sqrtf(p0 * p0 + p1 * p1 + p2 * p2 + p3 * p3) + 1e-12f);
    ((float4*)g_proj)[i] = make_float4(p0, p1, p2, p3);
    ((float4*)g_pn)[i]   = make_float4(p0 * inv, p1 * inv, p2 * inv, p3 * inv);
}

// ================= K5: pairwise adjacency-weighted sum =================
// 4 i-rows / thread, select+fma inner loop; NJC=64 with TJ=128 (R14 best).
__global__ __launch_bounds__(IT) void k_pair(int B)
{
    __shared__ float4 pns[TJ];
    __shared__ float4 prs[TJ];
    const int tid = threadIdx.x;
    const int ib  = blockIdx.x * (4 * IT);
    const int jc  = blockIdx.y;
    const int chunk = (B + NJC - 1) / NJC;
    const int jbeg = jc * chunk;
    const int jend = min(jbeg + chunk, B);

    const float4* pn   = (const float4*)g_pn;
    const float4* proj = (const float4*)g_proj;

    float4 v[4];
    int    idx[4];
    #pragma unroll
    for (int r = 0; r < 4; r++) {
        idx[r] = ib + r * IT + tid;
        v[r] = (idx[r] < B) ? pn[idx[r]] : make_float4(0.f, 0.f, 0.f, 0.f);
    }
    float w0[4] = {}, w1[4] = {}, w2[4] = {}, w3[4] = {};

    for (int jb = jbeg; jb < jend; jb += TJ) {
        int n = jend - jb;
        for (int t = tid; t < TJ; t += IT) {
            if (t < n) { pns[t] = pn[jb + t]; prs[t] = proj[jb + t]; }
            else       { pns[t] = make_float4(0.f, 0.f, 0.f, 0.f);
                         prs[t] = make_float4(0.f, 0.f, 0.f, 0.f); }
        }
        __syncthreads();
        #pragma unroll 4
        for (int jj = 0; jj < TJ; jj++) {
            float4 q  = pns[jj];
            float4 pj = prs[jj];
            #pragma unroll
            for (int r = 0; r < 4; r++) {
                float d = v[r].x * q.x + v[r].y * q.y + v[r].z * q.z + v[r].w * q.w;
                float s = (d * d >= 0.9f) ? 1.f : 0.f;
                w0[r] = fmaf(s, pj.x, w0[r]); w1[r] = fmaf(s, pj.y, w1[r]);
                w2[r] = fmaf(s, pj.z, w2[r]); w3[r] = fmaf(s, pj.w, w3[r]);
            }
        }
        __syncthreads();
    }
    float4* wp = (float4*)g_wp;
    #pragma unroll
    for (int r = 0; r < 4; r++)
        if (idx[r] < B)
            wp[(size_t)jc * B + idx[r]] = make_float4(w0[r], w1[r], w2[r], w3[r]);
}

// ================= K6: combine partials (subtract self), row sums, diff^2 ==========
__global__ __launch_bounds__(256) void k_combine(int B)
{
    int i = blockIdx.x * 256 + threadIdx.x;
    float ds = 0.f;
    if (i < B) {
        const float4* wpp = (const float4*)g_wp;
        float4 w = wpp[i];
        #pragma unroll
        for (int jc = 1; jc < NJC; jc++) {
            float4 t = wpp[(size_t)jc * B + i];
            w.x += t.x; w.y += t.y; w.z += t.z; w.w += t.w;
        }
        float4 p = ((const float4*)g_proj)[i];
        // subtract self-pair contribution (off-diagonal mask in reference)
        w.x -= p.x; w.y -= p.y; w.z -= p.z; w.w -= p.w;
        g_srow[i] = p.x + p.y + p.z + p.w + w.x + w.y + w.z + w.w;
        float d0 = p.x - w.x, d1 = p.y - w.y, d2 = p.z - w.z, d3 = p.w - w.w;
        ds = d0 * d0 + d1 * d1 + d2 * d2 + d3 * d3;
    }
    #pragma unroll
    for (int o = 16; o > 0; o >>= 1) ds += __shfl_down_sync(0xffffffffu, ds, o);
    __shared__ float red[8];
    int warp = threadIdx.x >> 5, lane = threadIdx.x & 31;
    if (lane == 0) red[warp] = ds;
    __syncthreads();
    if (threadIdx.x == 0) {
        float t = 0.f;
        #pragma unroll
        for (int w = 0; w < 8; w++) t += red[w];
        atomicAdd(&g_S, t);
    }
}

// ================= K7: kernel value + sigmoid epilogue =================
__global__ __launch_bounds__(256) void k_final(float* __restrict__ out, int B)
{
    int i = blockIdx.x * 256 + threadIdx.x;
    if (i >= B) return;
    float kv = expf(-g_S);              // GAMMA = 1
    float logit = g_srow[i] + kv;       // SHIFT = 0
    float p = 1.f / (1.f + expf(-logit));
    out[2 * i]     = p;
    out[2 * i + 1] = 1.f - p;
}

// ================= launcher =================
extern "C" void kernel_launch(void* const* d_in, const int* in_sizes, int n_in,
                              void* d_out, int out_size)
{
    const float* x   = (const float*)d_in[0];
    const float* c1w = (const float*)d_in[1];
    const float* c1b = (const float*)d_in[2];
    const float* c2w = (const float*)d_in[3];
    const float* c2b = (const float*)d_in[4];
    const float* f1w = (const float*)d_in[5];
    const float* f1b = (const float*)d_in[6];
    const float* f2w = (const float*)d_in[7];
    const float* f2b = (const float*)d_in[8];
    const float* gam = (const float*)d_in[9];
    const float* bet = (const float*)d_in[10];
    float* out = (float*)d_out;

    const int B = in_sizes[0] / 784;

    k_conv<<<B, 128>>>(x, c1w, c1b, c2w, c2b);
    k_fc<<<(B + 63) / 64, 256>>>(f1w, f1b, f2w, f2b, B);
    k_bnstats<<<1, 1024>>>(B);
    k_bnapply<<<(B + 255) / 256, 256>>>(gam, bet, B);
    dim3 gp((B + 4 * IT - 1) / (4 * IT), NJC);
    k_pair<<<gp, IT>>>(B);
    k_combine<<<(B + 255) / 256, 256>>>(B);
    k_final<<<(B + 255) / 256, 256>>>(out, B);
}

// round 16
// speedup vs baseline: 1.0757x; 1.0014x over previous
#include <cuda_runtime.h>
#include <math.h>

#define BMAX 8192
#define NJC 64
#define IT 128
#define TJ 128

// h1 padded layout (R8 win): row stride 22, channel stride 352.
#define H1S 22
#define H1C 352

// ---------------- scratch (device globals: no allocation allowed) ----------------
__device__ float  g_feat[BMAX * 784];
__device__ __align__(16) float g_proj_raw[BMAX * 4];
__device__ __align__(16) float g_proj[BMAX * 4];
__device__ __align__(16) float g_pn[BMAX * 4];
__device__ float  g_stats[8];
__device__ __align__(16) float g_wp[NJC * BMAX * 4];
__device__ float  g_srow[BMAX];
__device__ float  g_S;

// ================= K1: conv1+relu+pool + conv2+relu+pool (TWO images / block) ========
// Per-image compute identical to R15 (bit-exact). 256 threads = 2 half-blocks of 128;
// each half-block processes one image in its own xp/h1 slice. Weights loaded once
// per block -> per-image fixed cost (weight LDG, barriers, launch) halves.
__global__ __launch_bounds__(256) void k_conv(
    const float* __restrict__ x, const float* __restrict__ w1, const float* __restrict__ b1,
    const float* __restrict__ w2, const float* __restrict__ b2, int B)
{
    __shared__ __align__(16) float xp[2][30 * 30];
    __shared__ __align__(16) float h1[2][8 * H1C];
    __shared__ __align__(16) float sw1[72];
    __shared__ __align__(16) float sw2[1152];
    __shared__ float sb1[8], sb2[16];

    const int tid  = threadIdx.x;
    const int half = tid >> 7;          // 0 or 1: which image
    const int l    = tid & 127;         // lane within half-block
    const int img  = blockIdx.x * 2 + half;
    const bool act = (img < B);

    // --- setup (one barrier): weights (whole block) + per-image halo/interior ---
    if (tid < 72) sw1[tid] = w1[tid];
    if (tid < 8)  sb1[tid] = b1[tid];
    for (int i = tid; i < 1152; i += 256) sw2[i] = w2[i];
    if (tid < 16) sb2[tid] = b2[tid];

    float* xph = xp[half];
    float* h1h = h1[half];
    if (act) {
        // xp border: rows 0,29 (30 each) + cols 0,29 of rows 1..28 (28 each) = 116
        if (l < 116) {
            int r, c;
            if (l < 30)      { r = 0;  c = l; }
            else if (l < 60) { r = 29; c = l - 30; }
            else if (l < 88) { r = l - 60 + 1; c = 0; }
            else             { r = l - 88 + 1; c = 29; }
            xph[r * 30 + c] = 0.f;
        }
        // h1 border ring per channel: 60 entries per channel
        for (int i = l; i < 8 * 60; i += 128) {
            int ch = i / 60, e = i - ch * 60;
            int r, c;
            if (e < 16)      { r = 0;  c = e; }
            else if (e < 32) { r = 15; c = e - 16; }
            else if (e < 46) { r = e - 32 + 1; c = 0; }
            else             { r = e - 46 + 1; c = 15; }
            h1h[ch * H1C + r * H1S + c] = 0.f;
        }
        const float* xi = x + (size_t)img * 784;
        for (int i = l; i < 784; i += 128) {
            int y = i / 28, xx = i % 28;
            xph[(y + 1) * 30 + (xx + 1)] = xi[i];
        }
    }
    __syncthreads();

    // conv1 (1->8) + relu + pool: thread computes channels (c, c+4) at position p.
    if (act) {
        for (int idx = l; idx < 4 * 196; idx += 128) {
            int c = idx / 196, p = idx % 196;
            int py = p / 14, px = p % 14;
            int y0 = 2 * py, x0 = 2 * px;
            float v[4][4];
            #pragma unroll
            for (int dy = 0; dy < 4; dy++) {
                const float2* rp = (const float2*)(xph + (y0 + dy) * 30 + x0);
                float2 a = rp[0], b = rp[1];
                v[dy][0] = a.x; v[dy][1] = a.y; v[dy][2] = b.x; v[dy][3] = b.y;
            }
            const float* wa = sw1 + c * 9;
            const float* wb = sw1 + (c + 4) * 9;
            float a00 = 0.f, a01 = 0.f, a10 = 0.f, a11 = 0.f;
            float b00 = 0.f, b01 = 0.f, b10 = 0.f, b11 = 0.f;
            #pragma unroll
            for (int dy = 0; dy < 3; dy++)
                #pragma unroll
                for (int dx = 0; dx < 3; dx++) {
                    float wwa = wa[dy * 3 + dx];
                    float wwb = wb[dy * 3 + dx];
                    a00 += wwa * v[dy][dx];
                    a01 += wwa * v[dy][dx + 1];
                    a10 += wwa * v[dy + 1][dx];
                    a11 += wwa * v[dy + 1][dx + 1];
                    b00 += wwb * v[dy][dx];
                    b01 += wwb * v[dy][dx + 1];
                    b10 += wwb * v[dy + 1][dx];
                    b11 += wwb * v[dy + 1][dx + 1];
                }
            float ma = fmaxf(fmaxf(a00, a01), fmaxf(a10, a11)) + sb1[c];
            float mb = fmaxf(fmaxf(b00, b01), fmaxf(b10, b11)) + sb1[c + 4];
            h1h[c * H1C + (py + 1) * H1S + (px + 1)]       = fmaxf(ma, 0.f);
            h1h[(c + 4) * H1C + (py + 1) * H1S + (px + 1)] = fmaxf(mb, 0.f);
        }
    }
    __syncthreads();

    // conv2 (8->16) + relu + pool: thread computes channels (co, co+8) at position p.
    if (act) {
        float* fo = g_feat + (size_t)img * 784;
        for (int idx = l; idx < 8 * 49; idx += 128) {
            int co = idx / 49, p = idx % 49;
            int py = p / 7, px = p % 7;
            int y0 = 2 * py, x0 = 2 * px;
            float a00 = 0.f, a01 = 0.f, a10 = 0.f, a11 = 0.f;
            float b00 = 0.f, b01 = 0.f, b10 = 0.f, b11 = 0.f;
            #pragma unroll
            for (int ci = 0; ci < 8; ci++) {
                const float* wa = sw2 + (co * 8 + ci) * 9;
                const float* wb = sw2 + ((co + 8) * 8 + ci) * 9;
                const float* hb = h1h + ci * H1C;
                float v[4][4];
                #pragma unroll
                for (int dy = 0; dy < 4; dy++) {
                    const float2* rp = (const float2*)(hb + (y0 + dy) * H1S + x0);
                    float2 a = rp[0], b = rp[1];
                    v[dy][0] = a.x; v[dy][1] = a.y; v[dy][2] = b.x; v[dy][3] = b.y;
                }
                #pragma unroll
                for (int dy = 0; dy < 3; dy++)
                    #pragma unroll
                    for (int dx = 0; dx < 3; dx++) {
                        float wwa = wa[dy * 3 + dx];
                        float wwb = wb[dy * 3 + dx];
                        a00 += wwa * v[dy][dx];
                        a01 += wwa * v[dy][dx + 1];
                        a10 += wwa * v[dy + 1][dx];
                        a11 += wwa * v[dy + 1][dx + 1];
                        b00 += wwb * v[dy][dx];
                        b01 += wwb * v[dy][dx + 1];
                        b10 += wwb * v[dy + 1][dx];
                        b11 += wwb * v[dy + 1][dx + 1];
                    }
            }
            float ma = fmaxf(fmaxf(a00, a01), fmaxf(a10, a11)) + sb2[co];
            float mb = fmaxf(fmaxf(b00, b01), fmaxf(b10, b11)) + sb2[co + 8];
            fo[co * 49 + py * 7 + px]       = fmaxf(ma, 0.f);
            fo[(co + 8) * 49 + py * 7 + px] = fmaxf(mb, 0.f);
        }
    }
}

// ================= K2: fc1 (784->64, relu) + fc2 (64->4), 64 images / block ==========
#define KT 56
__global__ __launch_bounds__(256) void k_fc(
    const float* __restrict__ w1, const float* __restrict__ b1,
    const float* __restrict__ w2, const float* __restrict__ b2, int B)
{
    __shared__ float As[64][KT + 1];
    __shared__ float Ws[64][KT + 1];
    __shared__ float Hs[64][65];

    const int i0 = blockIdx.x * 64;
    const int tid = threadIdx.x;
    const int tx = tid & 15, ty = tid >> 4;

    float acc[4][4] = {};

    for (int k0 = 0; k0 < 784; k0 += KT) {
        for (int e = tid; e < 64 * KT; e += 256) {
            int r = e / KT, kk = e - r * KT;
            int row = i0 + r;
            As[r][kk] = (row < B) ? g_feat[(size_t)row * 784 + k0 + kk] : 0.f;
            Ws[r][kk] = w1[r * 784 + k0 + kk];
        }
        __syncthreads();
        #pragma unroll 4
        for (int kk = 0; kk < KT; kk++) {
            float a[4], b[4];
            #pragma unroll
            for (int r = 0; r < 4; r++) a[r] = As[ty * 4 + r][kk];
            #pragma unroll
            for (int c = 0; c < 4; c++) b[c] = Ws[tx * 4 + c][kk];
            #pragma unroll
            for (int r = 0; r < 4; r++)
                #pragma unroll
                for (int c = 0; c < 4; c++)
                    acc[r][c] += a[r] * b[c];
        }
        __syncthreads();
    }

    #pragma unroll
    for (int r = 0; r < 4; r++)
        #pragma unroll
        for (int c = 0; c < 4; c++) {
            int o = tx * 4 + c;
            Hs[ty * 4 + r][o] = fmaxf(acc[r][c] + b1[o], 0.f);
        }
    __syncthreads();

    int m = tid >> 2, c4 = tid & 3;
    if (i0 + m < B) {
        float s = b2[c4];
        #pragma unroll
        for (int o = 0; o < 64; o++) s += w2[c4 * 64 + o] * Hs[m][o];
        g_proj_raw[(size_t)(i0 + m) * 4 + c4] = s;
    }
}

// ================= K3: batchnorm stats (single block) =================
__global__ __launch_bounds__(1024) void k_bnstats(int B)
{
    __shared__ float red[32][8];
    const int tid = threadIdx.x;
    float s0 = 0, s1 = 0, s2 = 0, s3 = 0, q0 = 0, q1 = 0, q2 = 0, q3 = 0;
    const float4* pr = (const float4*)g_proj_raw;
    for (int i = tid; i < B; i += 1024) {
        float4 v = pr[i];
        s0 += v.x; s1 += v.y; s2 += v.z; s3 += v.w;
        q0 += v.x * v.x; q1 += v.y * v.y; q2 += v.z * v.z; q3 += v.w * v.w;
    }
    #pragma unroll
    for (int o = 16; o > 0; o >>= 1) {
        s0 += __shfl_down_sync(0xffffffffu, s0, o);
        s1 += __shfl_down_sync(0xffffffffu, s1, o);
        s2 += __shfl_down_sync(0xffffffffu, s2, o);
        s3 += __shfl_down_sync(0xffffffffu, s3, o);
        q0 += __shfl_down_sync(0xffffffffu, q0, o);
        q1 += __shfl_down_sync(0xffffffffu, q1, o);
        q2 += __shfl_down_sync(0xffffffffu, q2, o);
        q3 += __shfl_down_sync(0xffffffffu, q3, o);
    }
    int warp = tid >> 5, lane = tid & 31;
    if (lane == 0) {
        red[warp][0] = s0; red[warp][1] = s1; red[warp][2] = s2; red[warp][3] = s3;
        red[warp][4] = q0; red[warp][5] = q1; red[warp][6] = q2; red[warp][7] = q3;
    }
    __syncthreads();
    if (tid < 8) {
        float a = 0.f;
        for (int w = 0; w < 32; w++) a += red[w][tid];
        red[0][tid] = a;
    }
    __syncthreads();
    if (tid < 4) {
        float invB = 1.f / (float)B;
        float mean = red[0][tid] * invB;
        float var  = red[0][4 + tid] * invB - mean * mean;
        g_stats[tid] = mean;
        g_stats[4 + tid] = rsqrtf(var + 1e-5f);
    }
    if (tid == 0) g_S = 0.f;
}

// ================= K4: apply BN + row-normalize =================
__global__ __launch_bounds__(256) void k_bnapply(
    const float* __restrict__ gamma, const float* __restrict__ beta, int B)
{
    int i = blockIdx.x * 256 + threadIdx.x;
    if (i >= B) return;
    float4 v = ((const float4*)g_proj_raw)[i];
    float p0 = (v.x - g_stats[0]) * g_stats[4] * gamma[0] + beta[0];
    float p1 = (v.y - g_stats[1]) * g_stats[5] * gamma[1] + beta[1];
    float p2 = (v.z - g_stats[2]) * g_stats[6] * gamma[2] + beta[2];
    float p3 = (v.w - g_stats[3]) * g_stats[7] * gamma[3] + beta[3];
    float inv = 1.f / (sqrtf(p0 * p0 + p1 * p1 + p2 * p2 + p3 * p3) + 1e-12f);
    ((float4*)g_proj)[i] = make_float4(p0, p1, p2, p3);
    ((float4*)g_pn)[i]   = make_float4(p0 * inv, p1 * inv, p2 * inv, p3 * inv);
}

// ================= K5: pairwise adjacency-weighted sum =================
// 4 i-rows / thread, select+fma inner loop; NJC=64 with TJ=128 (R14 best).
__global__ __launch_bounds__(IT) void k_pair(int B)
{
    __shared__ float4 pns[TJ];
    __shared__ float4 prs[TJ];
    const int tid = threadIdx.x;
    const int ib  = blockIdx.x * (4 * IT);
    const int jc  = blockIdx.y;
    const int chunk = (B + NJC - 1) / NJC;
    const int jbeg = jc * chunk;
    const int jend = min(jbeg + chunk, B);

    const float4* pn   = (const float4*)g_pn;
    const float4* proj = (const float4*)g_proj;

    float4 v[4];
    int    idx[4];
    #pragma unroll
    for (int r = 0; r < 4; r++) {
        idx[r] = ib + r * IT + tid;
        v[r] = (idx[r] < B) ? pn[idx[r]] : make_float4(0.f, 0.f, 0.f, 0.f);
    }
    float w0[4] = {}, w1[4] = {}, w2[4] = {}, w3[4] = {};

    for (int jb = jbeg; jb < jend; jb += TJ) {
        int n = jend - jb;
        for (int t = tid; t < TJ; t += IT) {
            if (t < n) { pns[t] = pn[jb + t]; prs[t] = proj[jb + t]; }
            else       { pns[t] = make_float4(0.f, 0.f, 0.f, 0.f);
                         prs[t] = make_float4(0.f, 0.f, 0.f, 0.f); }
        }
        __syncthreads();
        #pragma unroll 4
        for (int jj = 0; jj < TJ; jj++) {
            float4 q  = pns[jj];
            float4 pj = prs[jj];
            #pragma unroll
            for (int r = 0; r < 4; r++) {
                float d = v[r].x * q.x + v[r].y * q.y + v[r].z * q.z + v[r].w * q.w;
                float s = (d * d >= 0.9f) ? 1.f : 0.f;
                w0[r] = fmaf(s, pj.x, w0[r]); w1[r] = fmaf(s, pj.y, w1[r]);
                w2[r] = fmaf(s, pj.z, w2[r]); w3[r] = fmaf(s, pj.w, w3[r]);
            }
        }
        __syncthreads();
    }
    float4* wp = (float4*)g_wp;
    #pragma unroll
    for (int r = 0; r < 4; r++)
        if (idx[r] < B)
            wp[(size_t)jc * B + idx[r]] = make_float4(w0[r], w1[r], w2[r], w3[r]);
}

// ================= K6: combine partials (subtract self), row sums, diff^2 ==========
__global__ __launch_bounds__(256) void k_combine(int B)
{
    int i = blockIdx.x * 256 + threadIdx.x;
    float ds = 0.f;
    if (i < B) {
        const float4* wpp = (const float4*)g_wp;
        float4 w = wpp[i];
        #pragma unroll
        for (int jc = 1; jc < NJC; jc++) {
            float4 t = wpp[(size_t)jc * B + i];
            w.x += t.x; w.y += t.y; w.z += t.z; w.w += t.w;
        }
        float4 p = ((const float4*)g_proj)[i];
        // subtract self-pair contribution (off-diagonal mask in reference)
        w.x -= p.x; w.y -= p.y; w.z -= p.z; w.w -= p.w;
        g_srow[i] = p.x + p.y + p.z + p.w + w.x + w.y + w.z + w.w;
        float d0 = p.x - w.x, d1 = p.y - w.y, d2 = p.z - w.z, d3 = p.w - w.w;
        ds = d0 * d0 + d1 * d1 + d2 * d2 + d3 * d3;
    }
    #pragma unroll
    for (int o = 16; o > 0; o >>= 1) ds += __shfl_down_sync(0xffffffffu, ds, o);
    __shared__ float red[8];
    int warp = threadIdx.x >> 5, lane = threadIdx.x & 31;
    if (lane == 0) red[warp] = ds;
    __syncthreads();
    if (threadIdx.x == 0) {
        float t = 0.f;
        #pragma unroll
        for (int w = 0; w < 8; w++) t += red[w];
        atomicAdd(&g_S, t);
    }
}

// ================= K7: kernel value + sigmoid epilogue =================
__global__ __launch_bounds__(256) void k_final(float* __restrict__ out, int B)
{
    int i = blockIdx.x * 256 + threadIdx.x;
    if (i >= B) return;
    float kv = expf(-g_S);              // GAMMA = 1
    float logit = g_srow[i] + kv;       // SHIFT = 0
    float p = 1.f / (1.f + expf(-logit));
    out[2 * i]     = p;
    out[2 * i + 1] = 1.f - p;
}

// ================= launcher =================
extern "C" void kernel_launch(void* const* d_in, const int* in_sizes, int n_in,
                              void* d_out, int out_size)
{
    const float* x   = (const float*)d_in[0];
    const float* c1w = (const float*)d_in[1];
    const float* c1b = (const float*)d_in[2];
    const float* c2w = (const float*)d_in[3];
    const float* c2b = (const float*)d_in[4];
    const float* f1w = (const float*)d_in[5];
    const float* f1b = (const float*)d_in[6];
    const float* f2w = (const float*)d_in[7];
    const float* f2b = (const float*)d_in[8];
    const float* gam = (const float*)d_in[9];
    const float* bet = (const float*)d_in[10];
    float* out = (float*)d_out;

    const int B = in_sizes[0] / 784;

    k_conv<<<(B + 1) / 2, 256>>>(x, c1w, c1b, c2w, c2b, B);
    k_fc<<<(B + 63) / 64, 256>>>(f1w, f1b, f2w, f2b, B);
    k_bnstats<<<1, 1024>>>(B);
    k_bnapply<<<(B + 255) / 256, 256>>>(gam, bet, B);
    dim3 gp((B + 4 * IT - 1) / (4 * IT), NJC);
    k_pair<<<gp, IT>>>(B);
    k_combine<<<(B + 255) / 256, 256>>>(B);
    k_final<<<(B + 255) / 256, 256>>>(out, B);
}